// round 9
// baseline (speedup 1.0000x reference)
#include <cuda_runtime.h>
#include <math.h>

#define NMAX 50000
#define EMAX 1600000
#define HID  128
#define INC  16

// Scratch (allocation-free rule: __device__ globals)
__device__ __align__(16) float g_h [NMAX * HID];   // pre-aggregation features (x @ W)
__device__ __align__(16) float g_x1[NMAX * HID];   // conv1 output (post relu)
__device__ __align__(16) float g_x2[NMAX * HID];   // conv2 output (post relu)
__device__ float g_dinv[NMAX];         // deg^-1/2 (incl. self loop)
__device__ int   g_deg [NMAX];         // in-degree (excl. self loop)
__device__ int   g_rowptr[NMAX];       // CSR start offsets
__device__ int   g_cursor[NMAX];       // fill cursors
__device__ int   g_eidx[EMAX];         // CSR: source node per incoming edge
__device__ int   g_row [EMAX];         // normalized edge sources (int32)
__device__ int   g_col [EMAX];         // normalized edge targets (int32)
__device__ int   g_is64;               // dtype flag: 1 if edge_index is int64

// ---------------------------------------------------------------------------
// Detect edge_index dtype: int64 values < 2^31 have every odd 32-bit word == 0.
__global__ void k_dtype(const int* __restrict__ w, int nwords) {
    if (threadIdx.x == 0 && blockIdx.x == 0) {
        int lim = nwords < 256 ? nwords : 256;
        int all0 = 1;
        for (int i = 1; i < lim; i += 2)
            if (w[i] != 0) { all0 = 0; break; }
        g_is64 = all0;
    }
}

// Normalize edge indices to int32 with clamping; handles both dtypes.
__global__ void k_convert(const void* __restrict__ ei, int E, int n) {
    int e = blockIdx.x * blockDim.x + threadIdx.x;
    if (e >= E) return;
    int r, c;
    if (g_is64) {
        const long long* p = (const long long*)ei;
        r = (int)p[e];
        c = (int)p[(size_t)E + e];
    } else {
        const int* p = (const int*)ei;
        r = p[e];
        c = p[E + e];
    }
    if (r < 0) r = 0; if (r >= n) r = n - 1;
    if (c < 0) c = 0; if (c >= n) c = n - 1;
    g_row[e] = r;
    g_col[e] = c;
}

__global__ void k_zero(int n) {
    int i = blockIdx.x * blockDim.x + threadIdx.x;
    if (i < n) { g_deg[i] = 0; g_cursor[i] = 0; }
}

__global__ void k_count(int E) {
    int e = blockIdx.x * blockDim.x + threadIdx.x;
    if (e < E) atomicAdd(&g_deg[g_col[e]], 1);
}

// exclusive scan of g_deg -> g_rowptr; single block, 1024 threads
__global__ void k_scan(int n) {
    __shared__ int part[1024];
    int tid   = threadIdx.x;
    int chunk = (n + 1023) / 1024;
    int start = tid * chunk;
    int end   = start + chunk; if (end > n) end = n;
    int s = 0;
    for (int i = start; i < end; i++) s += g_deg[i];
    part[tid] = s;
    __syncthreads();
    for (int off = 1; off < 1024; off <<= 1) {
        int v = (tid >= off) ? part[tid - off] : 0;
        __syncthreads();
        part[tid] += v;
        __syncthreads();
    }
    int base = (tid == 0) ? 0 : part[tid - 1];
    for (int i = start; i < end; i++) {
        g_rowptr[i] = base;
        base += g_deg[i];
    }
}

__global__ void k_dinv(int n) {
    int i = blockIdx.x * blockDim.x + threadIdx.x;
    if (i < n) g_dinv[i] = rsqrtf((float)g_deg[i] + 1.0f);  // +1: self loop
}

__global__ void k_fill(int E) {
    int e = blockIdx.x * blockDim.x + threadIdx.x;
    if (e >= E) return;
    int c = g_col[e];
    int pos = g_rowptr[c] + atomicAdd(&g_cursor[c], 1);
    g_eidx[pos] = g_row[e];
}

// h = x @ conv1_w   (N x 16) @ (16 x 128); 16 nodes per block, 128 threads
__global__ void k_gemm1(const float* __restrict__ x, const float* __restrict__ w, int n) {
    __shared__ float xs[16 * INC];
    int base = blockIdx.x * 16;
    int tid  = threadIdx.x;
    for (int i = tid; i < 16 * INC; i += 128) {
        int node = base + i / INC;
        xs[i] = (node < n) ? x[node * INC + (i % INC)] : 0.f;
    }
    __syncthreads();
    float acc[16];
#pragma unroll
    for (int j = 0; j < 16; j++) acc[j] = 0.f;
#pragma unroll
    for (int k = 0; k < INC; k++) {
        float wv = w[k * HID + tid];
#pragma unroll
        for (int j = 0; j < 16; j++) acc[j] += xs[j * INC + k] * wv;
    }
    for (int j = 0; j < 16; j++) {
        int node = base + j;
        if (node < n) g_h[(size_t)node * HID + tid] = acc[j];
    }
}

// h = g_x1 @ conv2_w  (N x 128) @ (128 x 128); 8 nodes per block, 128 threads
__global__ void k_gemm2(const float* __restrict__ w, int n) {
    __shared__ float xs[8 * HID];
    int base = blockIdx.x * 8;
    int tid  = threadIdx.x;
    for (int i = tid; i < 8 * HID; i += 128) {
        int node = base + i / HID;
        xs[i] = (node < n) ? g_x1[(size_t)node * HID + (i % HID)] : 0.f;
    }
    __syncthreads();
    float acc[8];
#pragma unroll
    for (int j = 0; j < 8; j++) acc[j] = 0.f;
    for (int k = 0; k < HID; k++) {
        float wv = w[k * HID + tid];
#pragma unroll
        for (int j = 0; j < 8; j++) acc[j] += xs[j * HID + k] * wv;
    }
    for (int j = 0; j < 8; j++) {
        int node = base + j;
        if (node < n) g_h[(size_t)node * HID + tid] = acc[j];
    }
}

// Aggregation as gather: one warp per node, lane owns a float4 chunk.
// phase 0: g_h -> g_x1 ; phase 1: g_h -> g_x2
__global__ void k_gather(const float* __restrict__ b, int n, int phase) {
    int g    = blockIdx.x * blockDim.x + threadIdx.x;
    int i    = g >> 5;
    int lane = g & 31;
    if (i >= n) return;

    const float* __restrict__ h = g_h;
    float* __restrict__ out = (phase == 0) ? g_x1 : g_x2;

    float dc    = g_dinv[i];
    int   start = g_rowptr[i];
    int   cnt   = g_deg[i];

    float4 acc = make_float4(0.f, 0.f, 0.f, 0.f);
    for (int k = 0; k < cnt; k++) {
        int   s   = g_eidx[start + k];
        float nrm = g_dinv[s];
        float4 v  = reinterpret_cast<const float4*>(h + (size_t)s * HID)[lane];
        acc.x += v.x * nrm; acc.y += v.y * nrm;
        acc.z += v.z * nrm; acc.w += v.w * nrm;
    }
    // incoming edges carry dinv[s]*dinv[i]; factor dc out of the sum
    acc.x *= dc; acc.y *= dc; acc.z *= dc; acc.w *= dc;

    // self loop: h[i] * dinv[i]^2
    float4 hv = reinterpret_cast<const float4*>(h + (size_t)i * HID)[lane];
    float dcc = dc * dc;
    acc.x += hv.x * dcc; acc.y += hv.y * dcc;
    acc.z += hv.z * dcc; acc.w += hv.w * dcc;

    const float4 bv = reinterpret_cast<const float4*>(b)[lane];
    acc.x = fmaxf(acc.x + bv.x, 0.f);
    acc.y = fmaxf(acc.y + bv.y, 0.f);
    acc.z = fmaxf(acc.z + bv.z, 0.f);
    acc.w = fmaxf(acc.w + bv.w, 0.f);
    reinterpret_cast<float4*>(out + (size_t)i * HID)[lane] = acc;
}

// ---------------------------------------------------------------------------
// Fused MLP heads: gg (x: 16->32->16), a1 (x1: 128->16->16), a2 (x2: 128->16->16),
// fusion (48->64->32->1, sigmoid). One thread per node, weights in shared.
__global__ void k_mlp(const float* __restrict__ x,
                      const float* ln1w, const float* ln1b,
                      const float* ln2w, const float* ln2b,
                      const float* na1w, const float* na1b,
                      const float* na2w, const float* na2b,
                      const float* na3w, const float* na3b,
                      const float* na4w, const float* na4b,
                      const float* f1w,  const float* f1b,
                      const float* f2w,  const float* f2b,
                      const float* f3w,  const float* f3b,
                      float* __restrict__ out, int n) {
    __shared__ float s[10993];
    float* sln1  = s;          float* sln1b = s + 512;
    float* sln2  = s + 544;    float* sln2b = s + 1056;
    float* sna1  = s + 1072;   float* sna1b = s + 3120;
    float* sna2  = s + 3136;   float* sna2b = s + 3392;
    float* sna3  = s + 3408;   float* sna3b = s + 5456;
    float* sna4  = s + 5472;   float* sna4b = s + 5728;
    float* sf1   = s + 5744;   float* sf1b  = s + 8816;
    float* sf2   = s + 8880;   float* sf2b  = s + 10928;
    float* sf3   = s + 10960;  float* sf3b  = s + 10992;

    int tid = threadIdx.x;
    auto cp = [&](float* d, const float* src, int cnt) {
        for (int i = tid; i < cnt; i += blockDim.x) d[i] = src[i];
    };
    cp(sln1, ln1w, 512);  cp(sln1b, ln1b, 32);
    cp(sln2, ln2w, 512);  cp(sln2b, ln2b, 16);
    cp(sna1, na1w, 2048); cp(sna1b, na1b, 16);
    cp(sna2, na2w, 256);  cp(sna2b, na2b, 16);
    cp(sna3, na3w, 2048); cp(sna3b, na3b, 16);
    cp(sna4, na4w, 256);  cp(sna4b, na4b, 16);
    cp(sf1,  f1w, 3072);  cp(sf1b,  f1b, 64);
    cp(sf2,  f2w, 2048);  cp(sf2b,  f2b, 32);
    cp(sf3,  f3w, 32);    cp(sf3b,  f3b, 1);
    __syncthreads();

    int i = blockIdx.x * blockDim.x + tid;
    if (i >= n) return;

    float xf[48];

    // --- gg path ---
    {
        float xin[INC];
#pragma unroll
        for (int k = 0; k < INC; k++) xin[k] = x[(size_t)i * INC + k];
        float h32[32];
#pragma unroll
        for (int j = 0; j < 32; j++) {
            float a = sln1b[j];
#pragma unroll
            for (int k = 0; k < INC; k++) a += xin[k] * sln1[k * 32 + j];
            h32[j] = fmaxf(a, 0.f);
        }
#pragma unroll
        for (int j = 0; j < 16; j++) {
            float a = sln2b[j];
#pragma unroll
            for (int k = 0; k < 32; k++) a += h32[k] * sln2[k * 16 + j];
            xf[j] = fmaxf(a, 0.f);
        }
    }

    // --- a1 path (from x1) ---
    {
        float t[16];
#pragma unroll
        for (int j = 0; j < 16; j++) t[j] = sna1b[j];
        const float* xr = g_x1 + (size_t)i * HID;
        for (int k = 0; k < HID; k++) {
            float xv = xr[k];
#pragma unroll
            for (int j = 0; j < 16; j++) t[j] += xv * sna1[k * 16 + j];
        }
#pragma unroll
        for (int j = 0; j < 16; j++) t[j] = fmaxf(t[j], 0.f);
#pragma unroll
        for (int j = 0; j < 16; j++) {
            float a = sna2b[j];
#pragma unroll
            for (int k = 0; k < 16; k++) a += t[k] * sna2[k * 16 + j];
            xf[16 + j] = fmaxf(a, 0.f);
        }
    }

    // --- a2 path (from x2) ---
    {
        float t[16];
#pragma unroll
        for (int j = 0; j < 16; j++) t[j] = sna3b[j];
        const float* xr = g_x2 + (size_t)i * HID;
        for (int k = 0; k < HID; k++) {
            float xv = xr[k];
#pragma unroll
            for (int j = 0; j < 16; j++) t[j] += xv * sna3[k * 16 + j];
        }
#pragma unroll
        for (int j = 0; j < 16; j++) t[j] = fmaxf(t[j], 0.f);
#pragma unroll
        for (int j = 0; j < 16; j++) {
            float a = sna4b[j];
#pragma unroll
            for (int k = 0; k < 16; k++) a += t[k] * sna4[k * 16 + j];
            xf[32 + j] = fmaxf(a, 0.f);
        }
    }

    // --- fusion head ---
    float h64[64];
#pragma unroll
    for (int j = 0; j < 64; j++) {
        float a = sf1b[j];
#pragma unroll
        for (int k = 0; k < 48; k++) a += xf[k] * sf1[k * 64 + j];
        h64[j] = fmaxf(a, 0.f);
    }
    float h32b[32];
#pragma unroll
    for (int j = 0; j < 32; j++) {
        float a = sf2b[j];
#pragma unroll
        for (int k = 0; k < 64; k++) a += h64[k] * sf2[k * 32 + j];
        h32b[j] = fmaxf(a, 0.f);
    }
    float z = sf3b[0];
#pragma unroll
    for (int k = 0; k < 32; k++) z += h32b[k] * sf3[k];
    out[i] = 1.f / (1.f + expf(-z));
}

// ---------------------------------------------------------------------------
extern "C" void kernel_launch(void* const* d_in, const int* in_sizes, int n_in,
                              void* d_out, int out_size) {
    const float* x        = (const float*)d_in[0];
    const void*  ei       = d_in[1];               // int32 OR int64 — detected on device
    const float* conv1_w  = (const float*)d_in[2];
    const float* conv1_b  = (const float*)d_in[3];
    const float* conv2_w  = (const float*)d_in[4];
    const float* conv2_b  = (const float*)d_in[5];
    const float* ln1_w = (const float*)d_in[6];   const float* ln1_b = (const float*)d_in[7];
    const float* ln2_w = (const float*)d_in[8];   const float* ln2_b = (const float*)d_in[9];
    const float* na1_w = (const float*)d_in[10];  const float* na1_b = (const float*)d_in[11];
    const float* na2_w = (const float*)d_in[12];  const float* na2_b = (const float*)d_in[13];
    const float* na3_w = (const float*)d_in[14];  const float* na3_b = (const float*)d_in[15];
    const float* na4_w = (const float*)d_in[16];  const float* na4_b = (const float*)d_in[17];
    const float* f1_w  = (const float*)d_in[18];  const float* f1_b  = (const float*)d_in[19];
    const float* f2_w  = (const float*)d_in[20];  const float* f2_b  = (const float*)d_in[21];
    const float* f3_w  = (const float*)d_in[22];  const float* f3_b  = (const float*)d_in[23];

    int n = in_sizes[0] / INC;
    int E = in_sizes[1] / 2;        // element count is 2E for either dtype
    if (E > EMAX) E = EMAX;
    if (n > NMAX) n = NMAX;

    int eb = (E + 255) / 256;
    int nb = (n + 255) / 256;

    // ---- dtype detect + normalize edges ----
    k_dtype  <<<1, 32>>>((const int*)ei, E * 2);
    k_convert<<<eb, 256>>>(ei, E, n);

    // ---- CSR build ----
    k_zero  <<<nb, 256>>>(n);
    k_count <<<eb, 256>>>(E);
    k_scan  <<<1, 1024>>>(n);
    k_dinv  <<<nb, 256>>>(n);
    k_fill  <<<eb, 256>>>(E);

    int gather_blocks = (n * 32 + 255) / 256;

    // ---- conv1 ----
    k_gemm1  <<<(n + 15) / 16, 128>>>(x, conv1_w, n);
    k_gather <<<gather_blocks, 256>>>(conv1_b, n, 0);

    // ---- conv2 ----
    k_gemm2  <<<(n + 7) / 8, 128>>>(conv2_w, n);
    k_gather <<<gather_blocks, 256>>>(conv2_b, n, 1);

    // ---- heads + fusion ----
    k_mlp<<<(n + 127) / 128, 128>>>(x,
        ln1_w, ln1_b, ln2_w, ln2_b,
        na1_w, na1_b, na2_w, na2_b,
        na3_w, na3_b, na4_w, na4_b,
        f1_w, f1_b, f2_w, f2_b, f3_w, f3_b,
        (float*)d_out, n);
}